// round 5
// baseline (speedup 1.0000x reference)
#include <cuda_runtime.h>

// ---------------------------------------------------------------------------
// TransferSH R5: non-divergent vectorized gather.
//
// R4 put the 12 LDG.128 gathers inside a 4-way switch on (id & 3); random
// indexes made that switch diverge, serializing gather issue into up to 4
// predicated passes and capping memory-level parallelism (DRAM stuck at 65%).
// R5 issues all 12 float4 gathers unconditionally (full-warp, back-to-back),
// and keeps only the FMA accumulation in the switch (FMA pipe has 9x
// headroom). Bounds: window end at id=1999999 is exactly 90M floats.
//
// Output layout (float32): [ clipped colors (N*3) , mean_abs scalar (1) ]
// ---------------------------------------------------------------------------

__device__ float g_affine[12];   // row-major 3x4, eye added

#define SH_C0 0.28209479177387814f
#define SH_C1 0.4886025119029199f
#define SH_C2_0 1.0925484305920792f
#define SH_C2_1 (-1.0925484305920792f)
#define SH_C2_2 0.31539156525252005f
#define SH_C2_3 (-1.0925484305920792f)
#define SH_C2_4 0.5462742152960396f
#define SH_C3_0 (-0.5900435899266435f)
#define SH_C3_1 2.890611442640554f
#define SH_C3_2 (-0.4570457994644658f)
#define SH_C3_3 0.3731763325901154f
#define SH_C3_4 (-0.4570457994644658f)
#define SH_C3_5 1.445305721320277f
#define SH_C3_6 (-0.5900435899266435f)

// ---------------------------------------------------------------------------
// Kernel A: 1x16 -> 32 (LN, relu) -> 12 MLP, affine build, mean|.|
// ---------------------------------------------------------------------------
__global__ void affine_kernel(const float* __restrict__ glo,
                              const float* __restrict__ w1,
                              const float* __restrict__ b1,
                              const float* __restrict__ ln_w,
                              const float* __restrict__ ln_b,
                              const float* __restrict__ w2,
                              const float* __restrict__ b2,
                              float* __restrict__ out_scalar)
{
    if (threadIdx.x != 0 || blockIdx.x != 0) return;

    float g[16];
#pragma unroll
    for (int k = 0; k < 16; k++) g[k] = glo[k];

    float h[32];
    float mu = 0.f;
#pragma unroll
    for (int j = 0; j < 32; j++) {
        float acc = b1[j];
#pragma unroll
        for (int k = 0; k < 16; k++) acc += g[k] * w1[k * 32 + j];
        h[j] = acc;
        mu += acc;
    }
    mu *= (1.f / 32.f);
    float var = 0.f;
#pragma unroll
    for (int j = 0; j < 32; j++) {
        float d = h[j] - mu;
        var += d * d;
    }
    var *= (1.f / 32.f);
    float inv = rsqrtf(var + 1e-5f);
#pragma unroll
    for (int j = 0; j < 32; j++) {
        float v = (h[j] - mu) * inv * ln_w[j] + ln_b[j];
        h[j] = v > 0.f ? v : 0.f;
    }

    float s = 0.f;
#pragma unroll
    for (int c = 0; c < 12; c++) {
        float o = b2[c];
#pragma unroll
        for (int j = 0; j < 32; j++) o += h[j] * w2[j * 12 + c];
        o *= 1e-12f;
        s += fabsf(o);
        g_affine[c] = o;
    }
    g_affine[0]  += 1.f;
    g_affine[5]  += 1.f;
    g_affine[10] += 1.f;

    *out_scalar = s * (1.f / 12.f);
}

// ---------------------------------------------------------------------------
// Accumulate with compile-time row offset OFF (0..3) inside the pre-loaded
// 12 x float4 window. Only FMAs; no memory ops (loads are hoisted by caller).
// ---------------------------------------------------------------------------
template<int OFF>
__device__ __forceinline__ void accum(const float4 (&v)[12],
                                      const float* __restrict__ basis,
                                      float* __restrict__ col)
{
    float f[48];
#pragma unroll
    for (int j = 0; j < 12; j++) {
        f[4 * j + 0] = v[j].x;
        f[4 * j + 1] = v[j].y;
        f[4 * j + 2] = v[j].z;
        f[4 * j + 3] = v[j].w;
    }
#pragma unroll
    for (int c = 0; c < 3; c++) {
        float acc = 0.f;
#pragma unroll
        for (int k = 0; k < 15; k++)
            acc += f[OFF + c * 15 + k] * basis[k + 1];
        col[c] += acc;
    }
}

// ---------------------------------------------------------------------------
// Kernel B: per-point SH evaluation + gather + affine + clamp
// ---------------------------------------------------------------------------
__global__ void __launch_bounds__(256)
transfer_sh_kernel(const float* __restrict__ positions,   // (N,3)
                   const int*   __restrict__ indexes,     // (N,)
                   const float* __restrict__ cam_pos,     // (3,)
                   const float* __restrict__ base_sh,     // (NP,3,1)
                   const float* __restrict__ higher_sh,   // (NP,3,15)
                   float*       __restrict__ out,         // (N,3)
                   int n)
{
    int i = blockIdx.x * blockDim.x + threadIdx.x;
    if (i >= n) return;

    // ---- issue the index load, then all gathers, unconditionally ----
    int id = __ldg(indexes + i);

    long long fstart = (long long)id * 45;
    const float4* q = (const float4*)higher_sh + (fstart >> 2);

    float4 v[12];
#pragma unroll
    for (int j = 0; j < 12; j++) v[j] = __ldg(q + j);

    const float* brow = base_sh + (long long)id * 3;
    float b0 = __ldg(brow + 0);
    float b1v = __ldg(brow + 1);
    float b2v = __ldg(brow + 2);

    // ---- direction + SH basis (overlaps with gather latency) ----
    float cx = __ldg(cam_pos + 0);
    float cy = __ldg(cam_pos + 1);
    float cz = __ldg(cam_pos + 2);

    float dx = __ldg(positions + 3 * i + 0) - cx;
    float dy = __ldg(positions + 3 * i + 1) - cy;
    float dz = __ldg(positions + 3 * i + 2) - cz;
    float rinv = rsqrtf(dx * dx + dy * dy + dz * dz);
    float x = dx * rinv, y = dy * rinv, z = dz * rinv;

    float xx = x * x, yy = y * y, zz = z * z;
    float xy = x * y, yz = y * z, xz = x * z;

    float basis[16];
    basis[0]  = SH_C0;
    basis[1]  = -SH_C1 * y;
    basis[2]  =  SH_C1 * z;
    basis[3]  = -SH_C1 * x;
    basis[4]  = SH_C2_0 * xy;
    basis[5]  = SH_C2_1 * yz;
    basis[6]  = SH_C2_2 * (2.f * zz - xx - yy);
    basis[7]  = SH_C2_3 * xz;
    basis[8]  = SH_C2_4 * (xx - yy);
    basis[9]  = SH_C3_0 * y * (3.f * xx - yy);
    basis[10] = SH_C3_1 * xy * z;
    basis[11] = SH_C3_2 * y * (4.f * zz - xx - yy);
    basis[12] = SH_C3_3 * z * (2.f * zz - 3.f * xx - 3.f * yy);
    basis[13] = SH_C3_4 * x * (4.f * zz - xx - yy);
    basis[14] = SH_C3_5 * z * (xx - yy);
    basis[15] = SH_C3_6 * x * (xx - yy);

    float col[3];
    col[0] = b0  * basis[0] + 0.5f;
    col[1] = b1v * basis[0] + 0.5f;
    col[2] = b2v * basis[0] + 0.5f;

    // ---- FMA-only divergent section (cheap; fma pipe has 9x headroom) ----
    switch ((int)(fstart & 3)) {
        case 0: accum<0>(v, basis, col); break;
        case 1: accum<1>(v, basis, col); break;
        case 2: accum<2>(v, basis, col); break;
        default: accum<3>(v, basis, col); break;
    }

    // ---- affine + clamp + store ----
#pragma unroll
    for (int r = 0; r < 3; r++) {
        float o = g_affine[r * 4 + 0] * col[0]
                + g_affine[r * 4 + 1] * col[1]
                + g_affine[r * 4 + 2] * col[2]
                + g_affine[r * 4 + 3];
        o = fminf(fmaxf(o, 0.f), 1.f);
        out[3 * i + r] = o;
    }
}

// ---------------------------------------------------------------------------
// kernel_launch
// input order: positions, indexes, cam_pos, glo_feature, base_sh, higher_sh,
//              w1, b1, ln_w, ln_b, w2, b2
// ---------------------------------------------------------------------------
extern "C" void kernel_launch(void* const* d_in, const int* in_sizes, int n_in,
                              void* d_out, int out_size)
{
    const float* positions = (const float*)d_in[0];
    const int*   indexes   = (const int*)  d_in[1];
    const float* cam_pos   = (const float*)d_in[2];
    const float* glo       = (const float*)d_in[3];
    const float* base_sh   = (const float*)d_in[4];
    const float* higher_sh = (const float*)d_in[5];
    const float* w1        = (const float*)d_in[6];
    const float* b1        = (const float*)d_in[7];
    const float* ln_w      = (const float*)d_in[8];
    const float* ln_b      = (const float*)d_in[9];
    const float* w2        = (const float*)d_in[10];
    const float* b2        = (const float*)d_in[11];

    float* out = (float*)d_out;
    int n = in_sizes[0] / 3;   // positions is (N,3)

    float* out_scalar = out + (out_size - 1);

    affine_kernel<<<1, 32>>>(glo, w1, b1, ln_w, ln_b, w2, b2, out_scalar);

    int threads = 256;
    int blocks = (n + threads - 1) / threads;
    transfer_sh_kernel<<<blocks, threads>>>(positions, indexes, cam_pos,
                                            base_sh, higher_sh, out, n);
}

// round 6
// speedup vs baseline: 1.2021x; 1.2021x over previous
#include <cuda_runtime.h>

// ---------------------------------------------------------------------------
// TransferSH R6: R4 structure (gather inside offset switch; short float4 live
// ranges) + occupancy push.
//
// Evidence: R4 (divergent loads, 48 regs, 40 warps/SM) = 134us, DRAM 65%.
//           R5 (batched loads, 72 regs, 20 warps/SM)   = 173us, DRAM 49%.
// => latency hiding scales with warps/SM more than with per-warp load batching.
// R6: cap regs at 42 via __launch_bounds__(256,6) -> 48 warps/SM (75% occ),
// and trim true register need (no basis[0], 32-bit offsets) to avoid spills.
//
// Output layout (float32): [ clipped colors (N*3) , mean_abs scalar (1) ]
// ---------------------------------------------------------------------------

__device__ float g_affine[12];   // row-major 3x4, eye added

#define SH_C0 0.28209479177387814f
#define SH_C1 0.4886025119029199f
#define SH_C2_0 1.0925484305920792f
#define SH_C2_1 (-1.0925484305920792f)
#define SH_C2_2 0.31539156525252005f
#define SH_C2_3 (-1.0925484305920792f)
#define SH_C2_4 0.5462742152960396f
#define SH_C3_0 (-0.5900435899266435f)
#define SH_C3_1 2.890611442640554f
#define SH_C3_2 (-0.4570457994644658f)
#define SH_C3_3 0.3731763325901154f
#define SH_C3_4 (-0.4570457994644658f)
#define SH_C3_5 1.445305721320277f
#define SH_C3_6 (-0.5900435899266435f)

// ---------------------------------------------------------------------------
// Kernel A: 1x16 -> 32 (LN, relu) -> 12 MLP, affine build, mean|.|
// ---------------------------------------------------------------------------
__global__ void affine_kernel(const float* __restrict__ glo,
                              const float* __restrict__ w1,
                              const float* __restrict__ b1,
                              const float* __restrict__ ln_w,
                              const float* __restrict__ ln_b,
                              const float* __restrict__ w2,
                              const float* __restrict__ b2,
                              float* __restrict__ out_scalar)
{
    if (threadIdx.x != 0 || blockIdx.x != 0) return;

    float g[16];
#pragma unroll
    for (int k = 0; k < 16; k++) g[k] = glo[k];

    float h[32];
    float mu = 0.f;
#pragma unroll
    for (int j = 0; j < 32; j++) {
        float acc = b1[j];
#pragma unroll
        for (int k = 0; k < 16; k++) acc += g[k] * w1[k * 32 + j];
        h[j] = acc;
        mu += acc;
    }
    mu *= (1.f / 32.f);
    float var = 0.f;
#pragma unroll
    for (int j = 0; j < 32; j++) {
        float d = h[j] - mu;
        var += d * d;
    }
    var *= (1.f / 32.f);
    float inv = rsqrtf(var + 1e-5f);
#pragma unroll
    for (int j = 0; j < 32; j++) {
        float v = (h[j] - mu) * inv * ln_w[j] + ln_b[j];
        h[j] = v > 0.f ? v : 0.f;
    }

    float s = 0.f;
#pragma unroll
    for (int c = 0; c < 12; c++) {
        float o = b2[c];
#pragma unroll
        for (int j = 0; j < 32; j++) o += h[j] * w2[j * 12 + c];
        o *= 1e-12f;
        s += fabsf(o);
        g_affine[c] = o;
    }
    g_affine[0]  += 1.f;
    g_affine[5]  += 1.f;
    g_affine[10] += 1.f;

    *out_scalar = s * (1.f / 12.f);
}

// ---------------------------------------------------------------------------
// Gather + accumulate with compile-time row offset OFF (0..3) inside the
// aligned 12 x float4 window. Loads live only inside this (short live range).
// basis has 15 entries = reference basis[1..15].
// ---------------------------------------------------------------------------
template<int OFF>
__device__ __forceinline__ void gather_accum(const float4* __restrict__ q,
                                             const float* __restrict__ basis,
                                             float* __restrict__ col)
{
    float f[48];
#pragma unroll
    for (int j = 0; j < 12; j++) {
        float4 t = __ldg(q + j);
        f[4 * j + 0] = t.x;
        f[4 * j + 1] = t.y;
        f[4 * j + 2] = t.z;
        f[4 * j + 3] = t.w;
    }
#pragma unroll
    for (int c = 0; c < 3; c++) {
        float acc = 0.f;
#pragma unroll
        for (int k = 0; k < 15; k++)
            acc += f[OFF + c * 15 + k] * basis[k];
        col[c] += acc;
    }
}

// ---------------------------------------------------------------------------
// Kernel B: per-point SH evaluation + gather + affine + clamp
// ---------------------------------------------------------------------------
__global__ void __launch_bounds__(256, 6)
transfer_sh_kernel(const float* __restrict__ positions,   // (N,3)
                   const int*   __restrict__ indexes,     // (N,)
                   const float* __restrict__ cam_pos,     // (3,)
                   const float* __restrict__ base_sh,     // (NP,3,1)
                   const float* __restrict__ higher_sh,   // (NP,3,15)
                   float*       __restrict__ out,         // (N,3)
                   int n)
{
    int i = blockIdx.x * blockDim.x + threadIdx.x;
    if (i >= n) return;

    // index + base_sh gather issued early (overlaps with basis math)
    int id = __ldg(indexes + i);
    unsigned fstart = (unsigned)id * 45u;          // < 2^31, 32-bit math
    const float4* q = (const float4*)higher_sh + (fstart >> 2);

    const float* brow = base_sh + (unsigned)id * 3u;
    float b0 = __ldg(brow + 0);
    float b1v = __ldg(brow + 1);
    float b2v = __ldg(brow + 2);

    float dx = __ldg(positions + 3 * i + 0) - __ldg(cam_pos + 0);
    float dy = __ldg(positions + 3 * i + 1) - __ldg(cam_pos + 1);
    float dz = __ldg(positions + 3 * i + 2) - __ldg(cam_pos + 2);
    float rinv = rsqrtf(dx * dx + dy * dy + dz * dz);
    float x = dx * rinv, y = dy * rinv, z = dz * rinv;

    float xx = x * x, yy = y * y, zz = z * z;
    float xy = x * y, yz = y * z, xz = x * z;

    // basis[1..15] of the reference (DC term folded into col init)
    float basis[15];
    basis[0]  = -SH_C1 * y;
    basis[1]  =  SH_C1 * z;
    basis[2]  = -SH_C1 * x;
    basis[3]  = SH_C2_0 * xy;
    basis[4]  = SH_C2_1 * yz;
    basis[5]  = SH_C2_2 * (2.f * zz - xx - yy);
    basis[6]  = SH_C2_3 * xz;
    basis[7]  = SH_C2_4 * (xx - yy);
    basis[8]  = SH_C3_0 * y * (3.f * xx - yy);
    basis[9]  = SH_C3_1 * xy * z;
    basis[10] = SH_C3_2 * y * (4.f * zz - xx - yy);
    basis[11] = SH_C3_3 * z * (2.f * zz - 3.f * xx - 3.f * yy);
    basis[12] = SH_C3_4 * x * (4.f * zz - xx - yy);
    basis[13] = SH_C3_5 * z * (xx - yy);
    basis[14] = SH_C3_6 * x * (xx - yy);

    float col[3];
    col[0] = b0  * SH_C0 + 0.5f;
    col[1] = b1v * SH_C0 + 0.5f;
    col[2] = b2v * SH_C0 + 0.5f;

    switch (fstart & 3u) {
        case 0: gather_accum<0>(q, basis, col); break;
        case 1: gather_accum<1>(q, basis, col); break;
        case 2: gather_accum<2>(q, basis, col); break;
        default: gather_accum<3>(q, basis, col); break;
    }

    // affine + clamp + store
#pragma unroll
    for (int r = 0; r < 3; r++) {
        float o = g_affine[r * 4 + 0] * col[0]
                + g_affine[r * 4 + 1] * col[1]
                + g_affine[r * 4 + 2] * col[2]
                + g_affine[r * 4 + 3];
        o = fminf(fmaxf(o, 0.f), 1.f);
        out[3 * i + r] = o;
    }
}

// ---------------------------------------------------------------------------
// kernel_launch
// input order: positions, indexes, cam_pos, glo_feature, base_sh, higher_sh,
//              w1, b1, ln_w, ln_b, w2, b2
// ---------------------------------------------------------------------------
extern "C" void kernel_launch(void* const* d_in, const int* in_sizes, int n_in,
                              void* d_out, int out_size)
{
    const float* positions = (const float*)d_in[0];
    const int*   indexes   = (const int*)  d_in[1];
    const float* cam_pos   = (const float*)d_in[2];
    const float* glo       = (const float*)d_in[3];
    const float* base_sh   = (const float*)d_in[4];
    const float* higher_sh = (const float*)d_in[5];
    const float* w1        = (const float*)d_in[6];
    const float* b1        = (const float*)d_in[7];
    const float* ln_w      = (const float*)d_in[8];
    const float* ln_b      = (const float*)d_in[9];
    const float* w2        = (const float*)d_in[10];
    const float* b2        = (const float*)d_in[11];

    float* out = (float*)d_out;
    int n = in_sizes[0] / 3;   // positions is (N,3)

    float* out_scalar = out + (out_size - 1);

    affine_kernel<<<1, 32>>>(glo, w1, b1, ln_w, ln_b, w2, b2, out_scalar);

    int threads = 256;
    int blocks = (n + threads - 1) / threads;
    transfer_sh_kernel<<<blocks, threads>>>(positions, indexes, cam_pos,
                                            base_sh, higher_sh, out, n);
}